// round 16
// baseline (speedup 1.0000x reference)
#include <cuda_runtime.h>
#include <cuda_bf16.h>

// Problem shape (fixed by reference setup_inputs): B=8, N=8192, D=512.
// out[b, n]     = dot(s_bn, h_rl_bn) / (max(||s||,eps) * max(||h_rl||,eps))
// out[b, N + n] = dot(s_bn, h_fk_bn) / (max(||s||,eps) * max(||h_fk||,eps))
//
// Pure streaming: 402MB compulsory reads -> LTS-cap bound (~6.9TB/s).
// Structure distilled from R1-R11 measurements:
//  - two adjacent rows per warp, ALL 24 LDG.128 front-batched (R10 win),
//  - SEPARATE per-row reductions (interleaving measured slower in R11;
//    occupancy covers the tail, issue order of loads is what matters),
//  - evict-first (.cs) loads/stores,
//  - 128-thread CTAs at occ 4 (same 16 warps/SM as 256x2, but CTA
//    replacement granularity halves -> a straggler warp holds 4 slots
//    hostage instead of 8, closing duty-cycle gaps at CTA boundaries).

#define D_DIM  512
#define N_DIM  8192          // power of two -> row/N is a shift
#define EPS    1e-12f

__device__ __forceinline__ void reduce_and_store(float4 (&av)[4], float4 (&rv)[4],
                                                 float4 (&fv)[4],
                                                 int row, int lane,
                                                 float* __restrict__ out)
{
    float ss = 0.f, rr = 0.f, ff = 0.f, sr = 0.f, sf = 0.f;

    #pragma unroll
    for (int i = 0; i < 4; i++) {
        const float4 a = av[i], r = rv[i], f = fv[i];
        ss = fmaf(a.x, a.x, ss); ss = fmaf(a.y, a.y, ss);
        ss = fmaf(a.z, a.z, ss); ss = fmaf(a.w, a.w, ss);
        rr = fmaf(r.x, r.x, rr); rr = fmaf(r.y, r.y, rr);
        rr = fmaf(r.z, r.z, rr); rr = fmaf(r.w, r.w, rr);
        ff = fmaf(f.x, f.x, ff); ff = fmaf(f.y, f.y, ff);
        ff = fmaf(f.z, f.z, ff); ff = fmaf(f.w, f.w, ff);
        sr = fmaf(a.x, r.x, sr); sr = fmaf(a.y, r.y, sr);
        sr = fmaf(a.z, r.z, sr); sr = fmaf(a.w, r.w, sr);
        sf = fmaf(a.x, f.x, sf); sf = fmaf(a.y, f.y, sf);
        sf = fmaf(a.z, f.z, sf); sf = fmaf(a.w, f.w, sf);
    }

    #pragma unroll
    for (int off = 16; off > 0; off >>= 1) {
        ss += __shfl_xor_sync(0xFFFFFFFFu, ss, off);
        rr += __shfl_xor_sync(0xFFFFFFFFu, rr, off);
        ff += __shfl_xor_sync(0xFFFFFFFFu, ff, off);
        sr += __shfl_xor_sync(0xFFFFFFFFu, sr, off);
        sf += __shfl_xor_sync(0xFFFFFFFFu, sf, off);
    }

    if (lane == 0) {
        const float ns = fmaxf(sqrtf(ss), EPS);
        const float nr = fmaxf(sqrtf(rr), EPS);
        const float nf = fmaxf(sqrtf(ff), EPS);
        const int b = row >> 13;             // row / 8192
        const int n = row & (N_DIM - 1);     // row % 8192
        float* ob = out + (size_t)b * (2 * N_DIM);
        __stcs(&ob[n],         sr / (ns * nr));
        __stcs(&ob[N_DIM + n], sf / (ns * nf));
    }
}

__global__ __launch_bounds__(128, 4)
void cosine_rows2_kernel(const float* __restrict__ s,
                         const float* __restrict__ h_rl,
                         const float* __restrict__ h_fk,
                         float* __restrict__ out,
                         int n_rows)
{
    const int warps_per_block = blockDim.x >> 5;
    const int warp = blockIdx.x * warps_per_block + (threadIdx.x >> 5);
    const int lane = threadIdx.x & 31;

    const int row0 = warp * 2;
    const int row1 = row0 + 1;
    if (row0 >= n_rows) return;

    const size_t base0 = (size_t)row0 * D_DIM;
    const float4* __restrict__ s40 = (const float4*)(s    + base0);
    const float4* __restrict__ r40 = (const float4*)(h_rl + base0);
    const float4* __restrict__ f40 = (const float4*)(h_fk + base0);
    const float4* __restrict__ s41 = s40 + (D_DIM / 4);
    const float4* __restrict__ r41 = r40 + (D_DIM / 4);
    const float4* __restrict__ f41 = f40 + (D_DIM / 4);

    const bool have1 = (row1 < n_rows);

    // Front-batch ALL 24 loads (12 per row) before any reduction.
    float4 a0[4], r0[4], f0[4], a1[4], r1[4], f1[4];
    #pragma unroll
    for (int i = 0; i < 4; i++) a0[i] = __ldcs(&s40[lane + i * 32]);
    #pragma unroll
    for (int i = 0; i < 4; i++) r0[i] = __ldcs(&r40[lane + i * 32]);
    #pragma unroll
    for (int i = 0; i < 4; i++) f0[i] = __ldcs(&f40[lane + i * 32]);
    if (have1) {
        #pragma unroll
        for (int i = 0; i < 4; i++) a1[i] = __ldcs(&s41[lane + i * 32]);
        #pragma unroll
        for (int i = 0; i < 4; i++) r1[i] = __ldcs(&r41[lane + i * 32]);
        #pragma unroll
        for (int i = 0; i < 4; i++) f1[i] = __ldcs(&f41[lane + i * 32]);
    }

    reduce_and_store(a0, r0, f0, row0, lane, out);
    if (have1)
        reduce_and_store(a1, r1, f1, row1, lane, out);
}

extern "C" void kernel_launch(void* const* d_in, const int* in_sizes, int n_in,
                              void* d_out, int out_size)
{
    const float* s    = (const float*)d_in[0];
    const float* h_rl = (const float*)d_in[1];
    const float* h_fk = (const float*)d_in[2];
    float* out = (float*)d_out;

    const int n_rows = in_sizes[0] / D_DIM;      // B*N = 65536

    const int threads = 128;                     // 4 warps -> 8 rows per block
    const int rows_per_block = 8;
    const int blocks = (n_rows + rows_per_block - 1) / rows_per_block;  // 8192
    cosine_rows2_kernel<<<blocks, threads>>>(s, h_rl, h_fk, out, n_rows);
}